// round 9
// baseline (speedup 1.0000x reference)
#include <cuda_runtime.h>
#include <cuda_bf16.h>
#include <cstdint>

// Problem constants
constexpr int NB = 8;     // batch
constexpr int NC = 512;   // channels
constexpr int NW = 2048;  // width (sequence)
constexpr int NQ = 64;    // C/8 (qk head dim)
constexpr int NM = 2 * NQ + NC;  // 640 fused output channels

// Scratch (device globals; allocation-free per harness rules).
__device__ __align__(16) uint16_t g_wh[(size_t)NM * NC];         // W planes [m][c]
__device__ __align__(16) uint16_t g_wl[(size_t)NM * NC];
__device__ __align__(16) uint16_t g_xth[(size_t)NB * NW * NC];   // x^T hi [b][w][c]
__device__ __align__(16) uint16_t g_xtl[(size_t)NB * NW * NC];   // x^T lo
__device__ __align__(16) uint16_t g_qkh[(size_t)NB * NW * 128];  // q|k hi [b][pos][ch]
__device__ __align__(16) uint16_t g_qkl[(size_t)NB * NW * 128];
__device__ __align__(16) uint16_t g_vh[(size_t)NB * NC * NW];    // v hi [b][c][j]
__device__ __align__(16) uint16_t g_vl[(size_t)NB * NC * NW];
__device__ __align__(16) float    g_att[(size_t)NB * NW * NW];   // energy S [b][i][j]
__device__ __align__(16) uint16_t g_ph[(size_t)NB * NW * NW];    // P hi [b][i][j]
__device__ __align__(16) uint16_t g_pl[(size_t)NB * NW * NW];

// ---------------- helpers ----------------------------------------------------

__device__ __forceinline__ uint32_t smem_u32(const void* p) {
    uint32_t a;
    asm("{ .reg .u64 t; cvta.to.shared.u64 t, %1; cvt.u32.u64 %0, t; }"
        : "=r"(a) : "l"(p));
    return a;
}

__device__ __forceinline__ uint32_t hi2(float a, float b) {
    return __byte_perm(__float_as_uint(a), __float_as_uint(b), 0x7632);
}
__device__ __forceinline__ float hitrunc(float a) {
    return __uint_as_float(__float_as_uint(a) & 0xFFFF0000u);
}
__device__ __forceinline__ uint32_t lo2(float a, float b) {
    __nv_bfloat162 t = __floats2bfloat162_rn(a - hitrunc(a), b - hitrunc(b));
    return *(uint32_t*)&t;
}
__device__ __forceinline__ unsigned short hi1(float a) {
    return (unsigned short)(__float_as_uint(a) >> 16);
}
__device__ __forceinline__ unsigned short lo1(float a) {
    __nv_bfloat16 t = __float2bfloat16_rn(a - hitrunc(a));
    return *(unsigned short*)&t;
}

#define LDSM_X4(R0, R1, R2, R3, A)                                            \
    asm volatile("ldmatrix.sync.aligned.m8n8.x4.shared.b16 {%0,%1,%2,%3}, [%4];" \
                 : "=r"(R0), "=r"(R1), "=r"(R2), "=r"(R3) : "r"(A))

#define MMA_BF16(c, a, b)                                                     \
    asm volatile("mma.sync.aligned.m16n8k16.row.col.f32.bf16.bf16.f32 "       \
                 "{%0,%1,%2,%3}, {%4,%5,%6,%7}, {%8,%9}, {%0,%1,%2,%3};"      \
                 : "+f"((c)[0]), "+f"((c)[1]), "+f"((c)[2]), "+f"((c)[3])     \
                 : "r"((a)[0]), "r"((a)[1]), "r"((a)[2]), "r"((a)[3]),        \
                   "r"((b)[0]), "r"((b)[1]))

// K=32-chunk geometry: row = [32 hi][32 lo][8 pad] bf16  (lo at +64 B)
constexpr int SROW = 72;                   // 144 B row stride
constexpr int TILE_HB = 128 * SROW * 2;    // 18432 B per operand tile
constexpr int GEMM_SMEM = 4 * TILE_HB;     // A0,B0,A1,B1 double buffer

// K=64 geometry (energy): row = [64 hi][64 lo][8 pad]    (lo at +128 B)
constexpr int SR64    = 136;               // 272 B row stride
constexpr int TILE64  = 128 * SR64 * 2;    // 34816 B
constexpr int EN_SMEM = 2 * TILE64;

// ---------------- warp-tile 64x16 stage: NKS k-steps of 16 ------------------
// acc[4][2][4]: mf (4 x m16), nf (2 x n8), 4 regs.
// NOTE: product-type loop is OUTERMOST so consecutive MMAs hit different acc
// registers (8-deep independence) — asm volatile blocks compiler reordering,
// so the instruction order written here IS the issue order.

template <int SR, int LOOFF, int NKS>
__device__ __forceinline__ void stage16(float acc[4][2][4], uint32_t aBase,
                                        uint32_t bBase, int wm, int wn,
                                        int lane) {
#pragma unroll
    for (int ks = 0; ks < NKS; ks++) {
        const int kb = ks * 16;
        uint32_t Ah[4][4], Al[4][4], Bh[2][2], Bl[2][2];
        const int am = wm * 64 + (lane & 15);
        const int ak = kb + ((lane >> 4) << 3);
#pragma unroll
        for (int mf = 0; mf < 4; mf++) {
            uint32_t addr = aBase + ((am + mf * 16) * SR + ak) * 2;
            LDSM_X4(Ah[mf][0], Ah[mf][1], Ah[mf][2], Ah[mf][3], addr);
            LDSM_X4(Al[mf][0], Al[mf][1], Al[mf][2], Al[mf][3], addr + LOOFF);
        }
        const int bn = wn * 16 + ((lane >> 4) << 3) + (lane & 7);
        const int bk = kb + (((lane >> 3) & 1) << 3);
        {
            uint32_t addr = bBase + (bn * SR + bk) * 2;
            LDSM_X4(Bh[0][0], Bh[0][1], Bh[1][0], Bh[1][1], addr);
            LDSM_X4(Bl[0][0], Bl[0][1], Bl[1][0], Bl[1][1], addr + LOOFF);
        }
        // product group 1: hi*hi (8 independent accumulators)
#pragma unroll
        for (int mf = 0; mf < 4; mf++)
#pragma unroll
            for (int nf = 0; nf < 2; nf++)
                MMA_BF16(acc[mf][nf], Ah[mf], Bh[nf]);
        // product group 2: hi*lo
#pragma unroll
        for (int mf = 0; mf < 4; mf++)
#pragma unroll
            for (int nf = 0; nf < 2; nf++)
                MMA_BF16(acc[mf][nf], Ah[mf], Bl[nf]);
        // product group 3: lo*hi
#pragma unroll
        for (int mf = 0; mf < 4; mf++)
#pragma unroll
            for (int nf = 0; nf < 2; nf++)
                MMA_BF16(acc[mf][nf], Al[mf], Bh[nf]);
    }
}

// ---------------- Kernel W: split weights into planes -----------------------

__global__ void __launch_bounds__(128)
wprep_kernel(const float* __restrict__ Wq, const float* __restrict__ Wk,
             const float* __restrict__ Wv) {
    const int m = blockIdx.x;
    const float* src;
    if (m < NQ)            src = Wq + (size_t)m * NC;
    else if (m < 2 * NQ)   src = Wk + (size_t)(m - NQ) * NC;
    else                   src = Wv + (size_t)(m - 2 * NQ) * NC;
    const int c4 = threadIdx.x * 4;
    float4 v = *(const float4*)(src + c4);
    size_t o = (size_t)m * NC + c4;
    *(uint2*)(g_wh + o) = make_uint2(hi2(v.x, v.y), hi2(v.z, v.w));
    *(uint2*)(g_wl + o) = make_uint2(lo2(v.x, v.y), lo2(v.z, v.w));
}

// ---------------- Kernel 0: transpose + split x -> [b][w][c] planes ---------
// (scalar phase-1 stores: 65-float row stride is not 16B aligned)

__global__ void __launch_bounds__(256)
transpose_x_kernel(const float* __restrict__ x) {
    __shared__ float s[64][65];
    const int b  = blockIdx.z;
    const int c0 = blockIdx.y * 64;
    const int w0 = blockIdx.x * 64;
    const int tid = threadIdx.x;

#pragma unroll
    for (int it = 0; it < 4; it++) {
        int c  = it * 16 + (tid >> 4);
        int w4 = (tid & 15) * 4;
        float4 v =
            *(const float4*)(x + ((size_t)b * NC + c0 + c) * NW + w0 + w4);
        s[c][w4 + 0] = v.x; s[c][w4 + 1] = v.y;
        s[c][w4 + 2] = v.z; s[c][w4 + 3] = v.w;
    }
    __syncthreads();

#pragma unroll
    for (int it = 0; it < 4; it++) {
        int w  = it * 16 + (tid >> 4);
        int c4 = (tid & 15) * 4;
        float f0 = s[c4 + 0][w], f1 = s[c4 + 1][w];
        float f2 = s[c4 + 2][w], f3 = s[c4 + 3][w];
        size_t o = ((size_t)b * NW + w0 + w) * NC + c0 + c4;
        *(uint2*)(g_xth + o) = make_uint2(hi2(f0, f1), hi2(f2, f3));
        *(uint2*)(g_xtl + o) = make_uint2(lo2(f0, f1), lo2(f2, f3));
    }
}

// ---------------- Kernel 1: QKV GEMM, 512 threads, 64x16 warp tiles ---------

__global__ void __launch_bounds__(512, 1)
qkv_mma_kernel(const float* __restrict__ bq, const float* __restrict__ bk,
               const float* __restrict__ bv) {
    extern __shared__ uint16_t smem[];
    const int b  = blockIdx.z;
    const int m0 = blockIdx.y * 128;
    const int w0 = blockIdx.x * 128;
    const int tid  = threadIdx.x;
    const int wid  = tid >> 5;
    const int lane = tid & 31;
    const int wm = wid >> 3, wn = wid & 7;

    const uint32_t sbase = smem_u32(smem);

    // loader: 4 threads per row, 8 elements each
    const int row = tid >> 2;
    const int c8  = (tid & 3) * 8;
    const uint16_t* rAh = g_wh + (size_t)(m0 + row) * NC;
    const uint16_t* rAl = g_wl + (size_t)(m0 + row) * NC;
    const uint16_t* rBh = g_xth + ((size_t)b * NW + w0 + row) * NC;
    const uint16_t* rBl = g_xtl + ((size_t)b * NW + w0 + row) * NC;

    float acc[4][2][4];
#pragma unroll
    for (int mf = 0; mf < 4; mf++)
#pragma unroll
        for (int nf = 0; nf < 2; nf++)
#pragma unroll
            for (int e = 0; e < 4; e++) acc[mf][nf][e] = 0.f;

    uint4 pah = *(const uint4*)(rAh + c8);
    uint4 pal = *(const uint4*)(rAl + c8);
    uint4 pbh = *(const uint4*)(rBh + c8);
    uint4 pbl = *(const uint4*)(rBl + c8);

    constexpr int NCH = NC / 32;   // 16
#pragma unroll 1
    for (int chunk = 0; chunk < NCH; chunk++) {
        const int p = chunk & 1;
        uint16_t* sA = smem + p * (2 * TILE_HB / 2);
        uint16_t* sB = sA + TILE_HB / 2;
        *(uint4*)(sA + row * SROW + c8)      = pah;
        *(uint4*)(sA + row * SROW + 32 + c8) = pal;
        *(uint4*)(sB + row * SROW + c8)      = pbh;
        *(uint4*)(sB + row * SROW + 32 + c8) = pbl;
        __syncthreads();

        if (chunk < NCH - 1) {
            const int kk = (chunk + 1) * 32;
            pah = *(const uint4*)(rAh + kk + c8);
            pal = *(const uint4*)(rAl + kk + c8);
            pbh = *(const uint4*)(rBh + kk + c8);
            pbl = *(const uint4*)(rBl + kk + c8);
        }

        const uint32_t aBase = sbase + p * 2 * TILE_HB;
        stage16<SROW, 64, 2>(acc, aBase, aBase + TILE_HB, wm, wn, lane);
    }

    // epilogue: q/k transposed planes, v natural planes
#pragma unroll
    for (int mf = 0; mf < 4; mf++) {
#pragma unroll
        for (int half = 0; half < 2; half++) {
            const int m = m0 + wm * 64 + mf * 16 + (lane >> 2) + 8 * half;
            if (m0 == 0 && m < 128) {
                const float bias = (m < NQ) ? bq[m] : bk[m - NQ];
#pragma unroll
                for (int nf = 0; nf < 2; nf++) {
                    const int n = w0 + wn * 16 + nf * 8 + ((lane & 3) << 1);
                    float y0 = acc[mf][nf][2 * half + 0] + bias;
                    float y1 = acc[mf][nf][2 * half + 1] + bias;
                    size_t o0 = ((size_t)b * NW + n) * 128 + m;
                    size_t o1 = o0 + 128;
                    g_qkh[o0] = hi1(y0); g_qkl[o0] = lo1(y0);
                    g_qkh[o1] = hi1(y1); g_qkl[o1] = lo1(y1);
                }
            } else if (m0 > 0) {
                const int c = m - 128;
                const float bias = bv[c];
#pragma unroll
                for (int nf = 0; nf < 2; nf++) {
                    const int n = w0 + wn * 16 + nf * 8 + ((lane & 3) << 1);
                    float y0 = acc[mf][nf][2 * half + 0] + bias;
                    float y1 = acc[mf][nf][2 * half + 1] + bias;
                    size_t o = ((size_t)b * NC + c) * NW + n;
                    *(uint32_t*)(g_vh + o) = hi2(y0, y1);
                    *(uint32_t*)(g_vl + o) = lo2(y0, y1);
                }
            }
        }
    }
}

// ---------------- Kernel 2: energy, 512 threads, K=64 single shot -----------

__global__ void __launch_bounds__(512, 1)
energy_mma_kernel() {
    extern __shared__ uint16_t smem[];
    const int b  = blockIdx.z;
    const int i0 = blockIdx.y * 128;
    const int j0 = blockIdx.x * 128;
    const int tid  = threadIdx.x;
    const int lane = tid & 31;
    const int wid  = tid >> 5;
    const int wm = wid >> 3, wn = wid & 7;

    const uint32_t sbase = smem_u32(smem);
    uint16_t* sA = smem;
    uint16_t* sB = smem + TILE64 / 2;

    const int row = tid >> 2;
    const int q16 = (tid & 3) * 16;
    {
        const uint16_t* qh = g_qkh + ((size_t)b * NW + i0 + row) * 128 + q16;
        const uint16_t* ql = g_qkl + ((size_t)b * NW + i0 + row) * 128 + q16;
        const uint16_t* kh = g_qkh + ((size_t)b * NW + j0 + row) * 128 + 64 + q16;
        const uint16_t* kl = g_qkl + ((size_t)b * NW + j0 + row) * 128 + 64 + q16;
#pragma unroll
        for (int q = 0; q < 2; q++) {
            *(uint4*)(sA + row * SR64 + q16 + 8 * q)      = *(const uint4*)(qh + 8 * q);
            *(uint4*)(sA + row * SR64 + 64 + q16 + 8 * q) = *(const uint4*)(ql + 8 * q);
            *(uint4*)(sB + row * SR64 + q16 + 8 * q)      = *(const uint4*)(kh + 8 * q);
            *(uint4*)(sB + row * SR64 + 64 + q16 + 8 * q) = *(const uint4*)(kl + 8 * q);
        }
    }
    __syncthreads();

    float acc[4][2][4];
#pragma unroll
    for (int mf = 0; mf < 4; mf++)
#pragma unroll
        for (int nf = 0; nf < 2; nf++)
#pragma unroll
            for (int e = 0; e < 4; e++) acc[mf][nf][e] = 0.f;

    stage16<SR64, 128, 4>(acc, sbase, sbase + TILE64, wm, wn, lane);

#pragma unroll
    for (int mf = 0; mf < 4; mf++) {
        const int m = i0 + wm * 64 + mf * 16 + (lane >> 2);
#pragma unroll
        for (int nf = 0; nf < 2; nf++) {
            const int n = j0 + wn * 16 + nf * 8 + ((lane & 3) << 1);
            size_t o0 = ((size_t)b * NW + m) * NW + n;
            *(float2*)(g_att + o0) = make_float2(acc[mf][nf][0], acc[mf][nf][1]);
            size_t o1 = o0 + (size_t)8 * NW;
            *(float2*)(g_att + o1) = make_float2(acc[mf][nf][2], acc[mf][nf][3]);
        }
    }
}

// ---------------- Kernel 3: row softmax, fp32 in, bf16 hi/lo planes out -----

__global__ void __launch_bounds__(256)
softmax_kernel() {
    __shared__ float red[8];
    const size_t row = blockIdx.x;
    const float* p = g_att + row * NW;
    const int tid = threadIdx.x;

    float4 v0 = *(const float4*)(p + tid * 8);
    float4 v1 = *(const float4*)(p + tid * 8 + 4);
    float e[8] = {v0.x, v0.y, v0.z, v0.w, v1.x, v1.y, v1.z, v1.w};

    float m = e[0];
#pragma unroll
    for (int i = 1; i < 8; i++) m = fmaxf(m, e[i]);
#pragma unroll
    for (int o = 16; o; o >>= 1) m = fmaxf(m, __shfl_xor_sync(0xffffffffu, m, o));
    if ((tid & 31) == 0) red[tid >> 5] = m;
    __syncthreads();
    m = red[0];
#pragma unroll
    for (int i = 1; i < 8; i++) m = fmaxf(m, red[i]);

    float s = 0.f;
#pragma unroll
    for (int i = 0; i < 8; i++) { e[i] = __expf(e[i] - m); s += e[i]; }
#pragma unroll
    for (int o = 16; o; o >>= 1) s += __shfl_xor_sync(0xffffffffu, s, o);
    __syncthreads();
    if ((tid & 31) == 0) red[tid >> 5] = s;
    __syncthreads();
    s = 0.f;
#pragma unroll
    for (int i = 0; i < 8; i++) s += red[i];

    float inv = 1.0f / s;
#pragma unroll
    for (int i = 0; i < 8; i++) e[i] *= inv;

    uint4 hv = make_uint4(hi2(e[0], e[1]), hi2(e[2], e[3]),
                          hi2(e[4], e[5]), hi2(e[6], e[7]));
    uint4 lv = make_uint4(lo2(e[0], e[1]), lo2(e[2], e[3]),
                          lo2(e[4], e[5]), lo2(e[6], e[7]));
    *(uint4*)(g_ph + row * NW + tid * 8) = hv;
    *(uint4*)(g_pl + row * NW + tid * 8) = lv;
}

// ---------------- Kernel 4: out GEMM, 512 threads, 64x16 warp tiles ---------
// out[c, i] = gamma * sum_j v[c,j] P[i,j] + x[c,i]

__global__ void __launch_bounds__(512, 1)
out_mma_kernel(const float* __restrict__ x, const float* __restrict__ gamma,
               float* __restrict__ out) {
    extern __shared__ uint16_t smem[];
    const int b  = blockIdx.z;
    const int c0 = blockIdx.x * 128;
    const int i0 = blockIdx.y * 128;
    const int tid  = threadIdx.x;
    const int wid  = tid >> 5;
    const int lane = tid & 31;
    const int wm = wid >> 3, wn = wid & 7;

    const uint32_t sbase = smem_u32(smem);

    const int row = tid >> 2;
    const int c8  = (tid & 3) * 8;
    const uint16_t* rAh = g_vh + ((size_t)b * NC + c0 + row) * NW;
    const uint16_t* rAl = g_vl + ((size_t)b * NC + c0 + row) * NW;
    const uint16_t* rBh = g_ph + ((size_t)b * NW + i0 + row) * NW;
    const uint16_t* rBl = g_pl + ((size_t)b * NW + i0 + row) * NW;

    float acc[4][2][4];
#pragma unroll
    for (int mf = 0; mf < 4; mf++)
#pragma unroll
        for (int nf = 0; nf < 2; nf++)
#pragma unroll
            for (int e = 0; e < 4; e++) acc[mf][nf][e] = 0.f;

    uint4 pah = *(const uint4*)(rAh + c8);
    uint4 pal = *(const uint4*)(rAl + c8);
    uint4 pbh = *(const uint4*)(rBh + c8);
    uint4 pbl = *(const uint4*)(rBl + c8);

    constexpr int NCH = NW / 32;   // 64
#pragma unroll 1
    for (int chunk = 0; chunk < NCH; chunk++) {
        const int p = chunk & 1;
        uint16_t* sA = smem + p * (2 * TILE_HB / 2);
        uint16_t* sB = sA + TILE_HB / 2;
        *(uint4*)(sA + row * SROW + c8)      = pah;
        *(uint4*)(sA + row * SROW + 32 + c8) = pal;
        *(uint4*)(sB + row * SROW + c8)      = pbh;
        *(uint4*)(sB + row * SROW + 32 + c8) = pbl;
        __syncthreads();

        if (chunk < NCH - 1) {
            const int kk = (chunk + 1) * 32;
            pah = *(const uint4*)(rAh + kk + c8);
            pal = *(const uint4*)(rAl + kk + c8);
            pbh = *(const uint4*)(rBh + kk + c8);
            pbl = *(const uint4*)(rBl + kk + c8);
        }

        const uint32_t aBase = sbase + p * 2 * TILE_HB;
        stage16<SROW, 64, 2>(acc, aBase, aBase + TILE_HB, wm, wn, lane);
    }

    const float gam = gamma[0];
#pragma unroll
    for (int mf = 0; mf < 4; mf++) {
        const int m = c0 + wm * 64 + mf * 16 + (lane >> 2);
#pragma unroll
        for (int nf = 0; nf < 2; nf++) {
            const int n = i0 + wn * 16 + nf * 8 + ((lane & 3) << 1);
            size_t o0 = ((size_t)b * NC + m) * NW + n;
            float2 xv0 = *(const float2*)(x + o0);
            *(float2*)(out + o0) = make_float2(fmaf(gam, acc[mf][nf][0], xv0.x),
                                               fmaf(gam, acc[mf][nf][1], xv0.y));
            size_t o1 = o0 + (size_t)8 * NW;
            float2 xv1 = *(const float2*)(x + o1);
            *(float2*)(out + o1) = make_float2(fmaf(gam, acc[mf][nf][2], xv1.x),
                                               fmaf(gam, acc[mf][nf][3], xv1.y));
        }
    }
}

// ---------------- launch ----------------------------------------------------

extern "C" void kernel_launch(void* const* d_in, const int* in_sizes, int n_in,
                              void* d_out, int out_size) {
    const float* x     = (const float*)d_in[0];
    const float* Wq    = (const float*)d_in[1];
    const float* bq    = (const float*)d_in[2];
    const float* Wk    = (const float*)d_in[3];
    const float* bk    = (const float*)d_in[4];
    const float* Wv    = (const float*)d_in[5];
    const float* bv    = (const float*)d_in[6];
    const float* gamma = (const float*)d_in[7];
    float* out = (float*)d_out;

    cudaFuncSetAttribute(qkv_mma_kernel,
                         cudaFuncAttributeMaxDynamicSharedMemorySize, GEMM_SMEM);
    cudaFuncSetAttribute(energy_mma_kernel,
                         cudaFuncAttributeMaxDynamicSharedMemorySize, EN_SMEM);
    cudaFuncSetAttribute(out_mma_kernel,
                         cudaFuncAttributeMaxDynamicSharedMemorySize, GEMM_SMEM);

    wprep_kernel<<<NM, 128>>>(Wq, Wk, Wv);
    transpose_x_kernel<<<dim3(NW / 64, NC / 64, NB), 256>>>(x);
    qkv_mma_kernel<<<dim3(NW / 128, 5, NB), 512, GEMM_SMEM>>>(bq, bk, bv);
    energy_mma_kernel<<<dim3(NW / 128, NW / 128, NB), 512, EN_SMEM>>>();
    softmax_kernel<<<NB * NW, 256>>>();
    out_mma_kernel<<<dim3(NC / 128, NW / 128, NB), 512, GEMM_SMEM>>>(x, gamma, out);
}

// round 10
// speedup vs baseline: 1.1745x; 1.1745x over previous
#include <cuda_runtime.h>
#include <cuda_fp16.h>
#include <cstdint>

// Problem constants
constexpr int NB = 8;     // batch
constexpr int NC = 512;   // channels
constexpr int NW = 2048;  // width (sequence)
constexpr int NQ = 64;    // C/8 (qk head dim)
constexpr int NM = 2 * NQ + NC;  // 640 fused output channels

// Scratch (device globals; allocation-free per harness rules).
// fp16 planes. A-role arrays keep hi+lo; B-role arrays are hi-only.
__device__ __align__(16) uint16_t g_wh[(size_t)NM * NC];         // W hi [m][c]
__device__ __align__(16) uint16_t g_wl[(size_t)NM * NC];         // W lo
__device__ __align__(16) uint16_t g_xth[(size_t)NB * NW * NC];   // x^T hi [b][w][c]
__device__ __align__(16) uint16_t g_qkh[(size_t)NB * NW * 128];  // q|k hi [b][pos][ch]
__device__ __align__(16) uint16_t g_qkl[(size_t)NB * NW * 64];   // q lo   [b][pos][ch<64]
__device__ __align__(16) uint16_t g_vh[(size_t)NB * NC * NW];    // v hi [b][c][j]
__device__ __align__(16) uint16_t g_vl[(size_t)NB * NC * NW];    // v lo
__device__ __align__(16) float    g_att[(size_t)NB * NW * NW];   // energy S [b][i][j]
__device__ __align__(16) uint16_t g_ph[(size_t)NB * NW * NW];    // P hi [b][i][j]

// ---------------- helpers ----------------------------------------------------

__device__ __forceinline__ uint32_t smem_u32(const void* p) {
    uint32_t a;
    asm("{ .reg .u64 t; cvta.to.shared.u64 t, %1; cvt.u32.u64 %0, t; }"
        : "=r"(a) : "l"(p));
    return a;
}

// pack fp16(a), fp16(b)
__device__ __forceinline__ uint32_t h2(float a, float b) {
    __half2 t = __floats2half2_rn(a, b);
    return *(uint32_t*)&t;
}
// pack fp16 residuals of (a, b)
__device__ __forceinline__ uint32_t l2f(float a, float b) {
    __half2 t = __floats2half2_rn(a, b);
    float2 f = __half22float2(t);
    __half2 r = __floats2half2_rn(a - f.x, b - f.y);
    return *(uint32_t*)&r;
}
__device__ __forceinline__ unsigned short h1(float a) {
    __half t = __float2half_rn(a);
    return *(unsigned short*)&t;
}
__device__ __forceinline__ unsigned short l1f(float a) {
    __half t = __float2half_rn(a);
    __half r = __float2half_rn(a - __half2float(t));
    return *(unsigned short*)&r;
}

#define LDSM_X4(R0, R1, R2, R3, A)                                            \
    asm volatile("ldmatrix.sync.aligned.m8n8.x4.shared.b16 {%0,%1,%2,%3}, [%4];" \
                 : "=r"(R0), "=r"(R1), "=r"(R2), "=r"(R3) : "r"(A))

#define MMA_F16(c, a, b)                                                      \
    asm volatile("mma.sync.aligned.m16n8k16.row.col.f32.f16.f16.f32 "         \
                 "{%0,%1,%2,%3}, {%4,%5,%6,%7}, {%8,%9}, {%0,%1,%2,%3};"      \
                 : "+f"((c)[0]), "+f"((c)[1]), "+f"((c)[2]), "+f"((c)[3])     \
                 : "r"((a)[0]), "r"((a)[1]), "r"((a)[2]), "r"((a)[3]),        \
                   "r"((b)[0]), "r"((b)[1]))

// K=32-chunk geometry:
//   A row: [32 hi][32 lo][8 pad]  -> stride 72 el (144 B, 9x16B: LDSM conflict-free)
//   B row: [32 hi][8 pad]         -> stride 40 el (80 B, 5x16B: conflict-free)
constexpr int SRA32 = 72;
constexpr int SRB32 = 40;
constexpr int TA32  = 128 * SRA32 * 2;   // 18432 B
constexpr int TB32  = 128 * SRB32 * 2;   // 10240 B
constexpr int ST32  = TA32 + TB32;       // 28672 B per stage
constexpr int GEMM_SMEM = 2 * ST32;      // 57344 B double-buffered

// K=64 geometry (energy): A row [64 hi][64 lo][8] = 136 el; B row [64 hi][8] = 72 el
constexpr int SRA64 = 136;
constexpr int SRB64 = 72;
constexpr int TA64  = 128 * SRA64 * 2;   // 34816 B
constexpr int TB64  = 128 * SRB64 * 2;   // 18432 B
constexpr int EN_SMEM = TA64 + TB64;     // 53248 B

// ---------------- warp-tile 64x32 stage, fp16 2-product ---------------------
// acc[4][4][4]: mf (4 x m16), nf (4 x n8).  C += Ah*Bh + Al*Bh.

template <int SRA, int SRB, int LOA, int NKS>
__device__ __forceinline__ void stage2(float acc[4][4][4], uint32_t aBase,
                                       uint32_t bBase, int wm, int wn,
                                       int lane) {
#pragma unroll
    for (int ks = 0; ks < NKS; ks++) {
        const int kb = ks * 16;
        uint32_t Ah[4][4], Al[4][4], Bh[4][2];
        const int am = wm * 64 + (lane & 15);
        const int ak = kb + ((lane >> 4) << 3);
#pragma unroll
        for (int mf = 0; mf < 4; mf++) {
            uint32_t addr = aBase + ((am + mf * 16) * SRA + ak) * 2;
            LDSM_X4(Ah[mf][0], Ah[mf][1], Ah[mf][2], Ah[mf][3], addr);
            LDSM_X4(Al[mf][0], Al[mf][1], Al[mf][2], Al[mf][3], addr + LOA);
        }
        const int bn = wn * 32 + ((lane >> 4) << 3) + (lane & 7);
        const int bk = kb + (((lane >> 3) & 1) << 3);
#pragma unroll
        for (int nfp = 0; nfp < 2; nfp++) {
            uint32_t addr = bBase + ((bn + nfp * 16) * SRB + bk) * 2;
            LDSM_X4(Bh[2 * nfp][0], Bh[2 * nfp][1],
                    Bh[2 * nfp + 1][0], Bh[2 * nfp + 1][1], addr);
        }
#pragma unroll
        for (int mf = 0; mf < 4; mf++)
#pragma unroll
            for (int nf = 0; nf < 4; nf++)
                MMA_F16(acc[mf][nf], Ah[mf], Bh[nf]);
#pragma unroll
        for (int mf = 0; mf < 4; mf++)
#pragma unroll
            for (int nf = 0; nf < 4; nf++)
                MMA_F16(acc[mf][nf], Al[mf], Bh[nf]);
    }
}

// ---------------- Kernel W: split weights into fp16 planes ------------------

__global__ void __launch_bounds__(128)
wprep_kernel(const float* __restrict__ Wq, const float* __restrict__ Wk,
             const float* __restrict__ Wv) {
    const int m = blockIdx.x;
    const float* src;
    if (m < NQ)            src = Wq + (size_t)m * NC;
    else if (m < 2 * NQ)   src = Wk + (size_t)(m - NQ) * NC;
    else                   src = Wv + (size_t)(m - 2 * NQ) * NC;
    const int c4 = threadIdx.x * 4;
    float4 v = *(const float4*)(src + c4);
    size_t o = (size_t)m * NC + c4;
    *(uint2*)(g_wh + o) = make_uint2(h2(v.x, v.y), h2(v.z, v.w));
    *(uint2*)(g_wl + o) = make_uint2(l2f(v.x, v.y), l2f(v.z, v.w));
}

// ---------------- Kernel 0: transpose x -> [b][w][c] fp16 hi plane ----------
// (scalar phase-1 stores: 65-float row stride is not 16B aligned)

__global__ void __launch_bounds__(256)
transpose_x_kernel(const float* __restrict__ x) {
    __shared__ float s[64][65];
    const int b  = blockIdx.z;
    const int c0 = blockIdx.y * 64;
    const int w0 = blockIdx.x * 64;
    const int tid = threadIdx.x;

#pragma unroll
    for (int it = 0; it < 4; it++) {
        int c  = it * 16 + (tid >> 4);
        int w4 = (tid & 15) * 4;
        float4 v =
            *(const float4*)(x + ((size_t)b * NC + c0 + c) * NW + w0 + w4);
        s[c][w4 + 0] = v.x; s[c][w4 + 1] = v.y;
        s[c][w4 + 2] = v.z; s[c][w4 + 3] = v.w;
    }
    __syncthreads();

#pragma unroll
    for (int it = 0; it < 4; it++) {
        int w  = it * 16 + (tid >> 4);
        int c4 = (tid & 15) * 4;
        float f0 = s[c4 + 0][w], f1 = s[c4 + 1][w];
        float f2 = s[c4 + 2][w], f3 = s[c4 + 3][w];
        size_t o = ((size_t)b * NW + w0 + w) * NC + c0 + c4;
        *(uint2*)(g_xth + o) = make_uint2(h2(f0, f1), h2(f2, f3));
    }
}

// ---------------- Kernel 1: QKV GEMM (fp16 2-product) -----------------------
// Y[m,w] = sum_c W[m,c] x[c,w] + bias.  A = W hi/lo, B = x^T hi.

__global__ void __launch_bounds__(256, 1)
qkv_mma_kernel(const float* __restrict__ bq, const float* __restrict__ bk,
               const float* __restrict__ bv) {
    extern __shared__ uint16_t smem[];
    const int b  = blockIdx.z;
    const int m0 = blockIdx.y * 128;
    const int w0 = blockIdx.x * 128;
    const int tid  = threadIdx.x;
    const int wid  = tid >> 5;
    const int lane = tid & 31;
    const int wm = wid >> 2, wn = wid & 3;

    const uint32_t sbase = smem_u32(smem);

    const int row = tid >> 1;
    const int c16 = (tid & 1) * 16;
    const uint16_t* rAh = g_wh + (size_t)(m0 + row) * NC + c16;
    const uint16_t* rAl = g_wl + (size_t)(m0 + row) * NC + c16;
    const uint16_t* rBh = g_xth + ((size_t)b * NW + w0 + row) * NC + c16;

    float acc[4][4][4];
#pragma unroll
    for (int mf = 0; mf < 4; mf++)
#pragma unroll
        for (int nf = 0; nf < 4; nf++)
#pragma unroll
            for (int e = 0; e < 4; e++) acc[mf][nf][e] = 0.f;

    uint4 pah[2], pal[2], pbh[2];
#pragma unroll
    for (int q = 0; q < 2; q++) {
        pah[q] = *(const uint4*)(rAh + 8 * q);
        pal[q] = *(const uint4*)(rAl + 8 * q);
        pbh[q] = *(const uint4*)(rBh + 8 * q);
    }

    constexpr int NCH = NC / 32;   // 16
#pragma unroll 1
    for (int chunk = 0; chunk < NCH; chunk++) {
        const int p = chunk & 1;
        uint16_t* sA = smem + p * (ST32 / 2);
        uint16_t* sB = sA + TA32 / 2;
#pragma unroll
        for (int q = 0; q < 2; q++) {
            *(uint4*)(sA + row * SRA32 + c16 + 8 * q)      = pah[q];
            *(uint4*)(sA + row * SRA32 + 32 + c16 + 8 * q) = pal[q];
            *(uint4*)(sB + row * SRB32 + c16 + 8 * q)      = pbh[q];
        }
        __syncthreads();

        if (chunk < NCH - 1) {
            const int kk = (chunk + 1) * 32;
#pragma unroll
            for (int q = 0; q < 2; q++) {
                pah[q] = *(const uint4*)(rAh + kk + 8 * q);
                pal[q] = *(const uint4*)(rAl + kk + 8 * q);
                pbh[q] = *(const uint4*)(rBh + kk + 8 * q);
            }
        }

        const uint32_t aBase = sbase + p * ST32;
        stage2<SRA32, SRB32, 64, 2>(acc, aBase, aBase + TA32, wm, wn, lane);
    }

    // epilogue: q hi+lo (transposed), k hi (transposed), v hi+lo planes
#pragma unroll
    for (int mf = 0; mf < 4; mf++) {
#pragma unroll
        for (int half = 0; half < 2; half++) {
            const int m = m0 + wm * 64 + mf * 16 + (lane >> 2) + 8 * half;
            if (m0 == 0 && m < 128) {
                const float bias = (m < NQ) ? bq[m] : bk[m - NQ];
#pragma unroll
                for (int nf = 0; nf < 4; nf++) {
                    const int n = w0 + wn * 32 + nf * 8 + ((lane & 3) << 1);
                    float y0 = acc[mf][nf][2 * half + 0] + bias;
                    float y1 = acc[mf][nf][2 * half + 1] + bias;
                    size_t o0 = ((size_t)b * NW + n) * 128 + m;
                    size_t o1 = o0 + 128;
                    g_qkh[o0] = h1(y0);
                    g_qkh[o1] = h1(y1);
                    if (m < NQ) {
                        size_t l0 = ((size_t)b * NW + n) * 64 + m;
                        g_qkl[l0]      = l1f(y0);
                        g_qkl[l0 + 64] = l1f(y1);
                    }
                }
            } else if (m0 > 0) {
                const int c = m - 128;
                const float bias = bv[c];
#pragma unroll
                for (int nf = 0; nf < 4; nf++) {
                    const int n = w0 + wn * 32 + nf * 8 + ((lane & 3) << 1);
                    float y0 = acc[mf][nf][2 * half + 0] + bias;
                    float y1 = acc[mf][nf][2 * half + 1] + bias;
                    size_t o = ((size_t)b * NC + c) * NW + n;
                    *(uint32_t*)(g_vh + o) = h2(y0, y1);
                    *(uint32_t*)(g_vl + o) = l2f(y0, y1);
                }
            }
        }
    }
}

// ---------------- Kernel 2: energy (fp16 2-product, K=64 single shot) -------
// S[i,j] = q[i,:] . k[j,:].  A = q hi/lo, B = k hi.

__global__ void __launch_bounds__(256, 1)
energy_mma_kernel() {
    extern __shared__ uint16_t smem[];
    const int b  = blockIdx.z;
    const int i0 = blockIdx.y * 128;
    const int j0 = blockIdx.x * 128;
    const int tid  = threadIdx.x;
    const int lane = tid & 31;
    const int wid  = tid >> 5;
    const int wm = wid >> 2, wn = wid & 3;

    const uint32_t sbase = smem_u32(smem);
    uint16_t* sA = smem;
    uint16_t* sB = smem + TA64 / 2;

    const int row = tid >> 1;
    const int h32 = (tid & 1) * 32;
    {
        const uint16_t* qh = g_qkh + ((size_t)b * NW + i0 + row) * 128 + h32;
        const uint16_t* ql = g_qkl + ((size_t)b * NW + i0 + row) * 64 + h32;
        const uint16_t* kh = g_qkh + ((size_t)b * NW + j0 + row) * 128 + 64 + h32;
#pragma unroll
        for (int q = 0; q < 4; q++) {
            *(uint4*)(sA + row * SRA64 + h32 + 8 * q)      = *(const uint4*)(qh + 8 * q);
            *(uint4*)(sA + row * SRA64 + 64 + h32 + 8 * q) = *(const uint4*)(ql + 8 * q);
            *(uint4*)(sB + row * SRB64 + h32 + 8 * q)      = *(const uint4*)(kh + 8 * q);
        }
    }
    __syncthreads();

    float acc[4][4][4];
#pragma unroll
    for (int mf = 0; mf < 4; mf++)
#pragma unroll
        for (int nf = 0; nf < 4; nf++)
#pragma unroll
            for (int e = 0; e < 4; e++) acc[mf][nf][e] = 0.f;

    stage2<SRA64, SRB64, 128, 4>(acc, sbase, sbase + TA64, wm, wn, lane);

#pragma unroll
    for (int mf = 0; mf < 4; mf++) {
        const int m = i0 + wm * 64 + mf * 16 + (lane >> 2);
#pragma unroll
        for (int nf = 0; nf < 4; nf++) {
            const int n = j0 + wn * 32 + nf * 8 + ((lane & 3) << 1);
            size_t o0 = ((size_t)b * NW + m) * NW + n;
            *(float2*)(g_att + o0) = make_float2(acc[mf][nf][0], acc[mf][nf][1]);
            size_t o1 = o0 + (size_t)8 * NW;
            *(float2*)(g_att + o1) = make_float2(acc[mf][nf][2], acc[mf][nf][3]);
        }
    }
}

// ---------------- Kernel 3: row softmax, fp32 in, fp16 hi plane out ---------

__global__ void __launch_bounds__(256)
softmax_kernel() {
    __shared__ float red[8];
    const size_t row = blockIdx.x;
    const float* p = g_att + row * NW;
    const int tid = threadIdx.x;

    float4 v0 = *(const float4*)(p + tid * 8);
    float4 v1 = *(const float4*)(p + tid * 8 + 4);
    float e[8] = {v0.x, v0.y, v0.z, v0.w, v1.x, v1.y, v1.z, v1.w};

    float m = e[0];
#pragma unroll
    for (int i = 1; i < 8; i++) m = fmaxf(m, e[i]);
#pragma unroll
    for (int o = 16; o; o >>= 1) m = fmaxf(m, __shfl_xor_sync(0xffffffffu, m, o));
    if ((tid & 31) == 0) red[tid >> 5] = m;
    __syncthreads();
    m = red[0];
#pragma unroll
    for (int i = 1; i < 8; i++) m = fmaxf(m, red[i]);

    float s = 0.f;
#pragma unroll
    for (int i = 0; i < 8; i++) { e[i] = __expf(e[i] - m); s += e[i]; }
#pragma unroll
    for (int o = 16; o; o >>= 1) s += __shfl_xor_sync(0xffffffffu, s, o);
    __syncthreads();
    if ((tid & 31) == 0) red[tid >> 5] = s;
    __syncthreads();
    s = 0.f;
#pragma unroll
    for (int i = 0; i < 8; i++) s += red[i];

    float inv = 1.0f / s;
#pragma unroll
    for (int i = 0; i < 8; i++) e[i] *= inv;

    *(uint4*)(g_ph + row * NW + tid * 8) =
        make_uint4(h2(e[0], e[1]), h2(e[2], e[3]),
                   h2(e[4], e[5]), h2(e[6], e[7]));
}

// ---------------- Kernel 4: out GEMM (fp16 2-product) -----------------------
// out[c,i] = gamma * sum_j v[c,j] P[i,j] + x[c,i].  A = v hi/lo, B = P hi.

__global__ void __launch_bounds__(256, 1)
out_mma_kernel(const float* __restrict__ x, const float* __restrict__ gamma,
               float* __restrict__ out) {
    extern __shared__ uint16_t smem[];
    const int b  = blockIdx.z;
    const int c0 = blockIdx.x * 128;
    const int i0 = blockIdx.y * 128;
    const int tid  = threadIdx.x;
    const int wid  = tid >> 5;
    const int lane = tid & 31;
    const int wm = wid >> 2, wn = wid & 3;

    const uint32_t sbase = smem_u32(smem);

    const int row = tid >> 1;
    const int c16 = (tid & 1) * 16;
    const uint16_t* rAh = g_vh + ((size_t)b * NC + c0 + row) * NW + c16;
    const uint16_t* rAl = g_vl + ((size_t)b * NC + c0 + row) * NW + c16;
    const uint16_t* rBh = g_ph + ((size_t)b * NW + i0 + row) * NW + c16;

    float acc[4][4][4];
#pragma unroll
    for (int mf = 0; mf < 4; mf++)
#pragma unroll
        for (int nf = 0; nf < 4; nf++)
#pragma unroll
            for (int e = 0; e < 4; e++) acc[mf][nf][e] = 0.f;

    uint4 pah[2], pal[2], pbh[2];
#pragma unroll
    for (int q = 0; q < 2; q++) {
        pah[q] = *(const uint4*)(rAh + 8 * q);
        pal[q] = *(const uint4*)(rAl + 8 * q);
        pbh[q] = *(const uint4*)(rBh + 8 * q);
    }

    constexpr int NCH = NW / 32;   // 64
#pragma unroll 1
    for (int chunk = 0; chunk < NCH; chunk++) {
        const int p = chunk & 1;
        uint16_t* sA = smem + p * (ST32 / 2);
        uint16_t* sB = sA + TA32 / 2;
#pragma unroll
        for (int q = 0; q < 2; q++) {
            *(uint4*)(sA + row * SRA32 + c16 + 8 * q)      = pah[q];
            *(uint4*)(sA + row * SRA32 + 32 + c16 + 8 * q) = pal[q];
            *(uint4*)(sB + row * SRB32 + c16 + 8 * q)      = pbh[q];
        }
        __syncthreads();

        if (chunk < NCH - 1) {
            const int kk = (chunk + 1) * 32;
#pragma unroll
            for (int q = 0; q < 2; q++) {
                pah[q] = *(const uint4*)(rAh + kk + 8 * q);
                pal[q] = *(const uint4*)(rAl + kk + 8 * q);
                pbh[q] = *(const uint4*)(rBh + kk + 8 * q);
            }
        }

        const uint32_t aBase = sbase + p * ST32;
        stage2<SRA32, SRB32, 64, 2>(acc, aBase, aBase + TA32, wm, wn, lane);
    }

    const float gam = gamma[0];
#pragma unroll
    for (int mf = 0; mf < 4; mf++) {
        const int m = c0 + wm * 64 + mf * 16 + (lane >> 2);
#pragma unroll
        for (int nf = 0; nf < 4; nf++) {
            const int n = i0 + wn * 32 + nf * 8 + ((lane & 3) << 1);
            size_t o0 = ((size_t)b * NC + m) * NW + n;
            float2 xv0 = *(const float2*)(x + o0);
            *(float2*)(out + o0) = make_float2(fmaf(gam, acc[mf][nf][0], xv0.x),
                                               fmaf(gam, acc[mf][nf][1], xv0.y));
            size_t o1 = o0 + (size_t)8 * NW;
            float2 xv1 = *(const float2*)(x + o1);
            *(float2*)(out + o1) = make_float2(fmaf(gam, acc[mf][nf][2], xv1.x),
                                               fmaf(gam, acc[mf][nf][3], xv1.y));
        }
    }
}

// ---------------- launch ----------------------------------------------------

extern "C" void kernel_launch(void* const* d_in, const int* in_sizes, int n_in,
                              void* d_out, int out_size) {
    const float* x     = (const float*)d_in[0];
    const float* Wq    = (const float*)d_in[1];
    const float* bq    = (const float*)d_in[2];
    const float* Wk    = (const float*)d_in[3];
    const float* bk    = (const float*)d_in[4];
    const float* Wv    = (const float*)d_in[5];
    const float* bv    = (const float*)d_in[6];
    const float* gamma = (const float*)d_in[7];
    float* out = (float*)d_out;

    cudaFuncSetAttribute(qkv_mma_kernel,
                         cudaFuncAttributeMaxDynamicSharedMemorySize, GEMM_SMEM);
    cudaFuncSetAttribute(energy_mma_kernel,
                         cudaFuncAttributeMaxDynamicSharedMemorySize, EN_SMEM);
    cudaFuncSetAttribute(out_mma_kernel,
                         cudaFuncAttributeMaxDynamicSharedMemorySize, GEMM_SMEM);

    wprep_kernel<<<NM, 128>>>(Wq, Wk, Wv);
    transpose_x_kernel<<<dim3(NW / 64, NC / 64, NB), 256>>>(x);
    qkv_mma_kernel<<<dim3(NW / 128, 5, NB), 256, GEMM_SMEM>>>(bq, bk, bv);
    energy_mma_kernel<<<dim3(NW / 128, NW / 128, NB), 256, EN_SMEM>>>();
    softmax_kernel<<<NB * NW, 256>>>();
    out_mma_kernel<<<dim3(NC / 128, NW / 128, NB), 256, GEMM_SMEM>>>(x, gamma, out);
}